// round 1
// baseline (speedup 1.0000x reference)
#include <cuda_runtime.h>
#include <cuda_bf16.h>

#define OUT_UNITS 128
#define MAX_ROWS  16384

// ---------------------------------------------------------------------------
// Scratch (device globals — no allocation allowed in kernel_launch)
// ---------------------------------------------------------------------------
__device__ int g_is64;                       // 1 if rows/cols are int64, 0 if int32
__device__ int g_row_start[MAX_ROWS + 1];    // CSR-style row offsets

// ---------------------------------------------------------------------------
// Kernel 1: detect index dtype.
// rows is sorted ascending over [0, 16384). If stored as int64 (little-endian),
// every odd 32-bit word is a zero high-half. If stored as int32, the words at
// odd indices near n/4, n/2, 3n/4 are sorted row ids ~4096/8192/12288 (nonzero).
// All probed indices are odd and < n, so they are in-bounds for both layouts.
// ---------------------------------------------------------------------------
__global__ void detect_dtype_kernel(const int* __restrict__ rows32, int n) {
    int j1 = (n / 2) | 1;
    int j2 = (n / 4) | 1;
    int j3 = (int)(((long long)3 * n / 4)) | 1;
    int s = rows32[j1] | rows32[j2] | rows32[j3];
    g_is64 = (s == 0) ? 1 : 0;
}

// ---------------------------------------------------------------------------
// Kernel 2: build row offsets from sorted COO rows.
// Segment for row r is [g_row_start[r], g_row_start[r+1]).
// ---------------------------------------------------------------------------
__global__ void build_offsets_kernel(const int* __restrict__ rows32, int nnz, int n_rows) {
    int k = blockIdx.x * blockDim.x + threadIdx.x;
    if (k >= nnz) return;
    const int is64 = g_is64;

    int r  = is64 ? rows32[2 * k] : rows32[k];
    int rp = (k == 0) ? -1 : (is64 ? rows32[2 * (k - 1)] : rows32[k - 1]);

    // Fill starts for all rows that begin at k (handles empty rows too).
    for (int j = rp + 1; j <= r && j <= n_rows; j++)
        g_row_start[j] = k;

    if (k == nnz - 1) {
        for (int j = r + 1; j <= n_rows; j++)
            g_row_start[j] = nnz;
    }
}

// ---------------------------------------------------------------------------
// Kernel 3: main SpMM. One CTA per output row; thread t owns output column t.
// Stage (value, col) pairs of this row's segment into smem, then accumulate
// coalesced gathers of W rows (512B per nnz, L2-resident).
// ---------------------------------------------------------------------------
__global__ void __launch_bounds__(OUT_UNITS)
spmm_kernel(const float* __restrict__ values,
            const float* __restrict__ w,
            const int*   __restrict__ cols32,
            float*       __restrict__ out) {
    const int r   = blockIdx.x;
    const int tid = threadIdx.x;
    const int is64 = g_is64;

    __shared__ float sval[128];
    __shared__ int   scol[128];

    const int lo = g_row_start[r];
    const int hi = g_row_start[r + 1];

    float acc = 0.0f;

    for (int base = lo; base < hi; base += 128) {
        const int m = min(128, hi - base);
        if (tid < m) {
            const int k = base + tid;
            sval[tid] = values[k];
            scol[tid] = is64 ? cols32[2 * k] : cols32[k];
        }
        __syncthreads();

        int i = 0;
        #pragma unroll 1
        for (; i + 4 <= m; i += 4) {
            // 4 independent coalesced W-row loads in flight (MLP vs L2 latency)
            const float v0 = sval[i + 0], v1 = sval[i + 1];
            const float v2 = sval[i + 2], v3 = sval[i + 3];
            const int   c0 = scol[i + 0], c1 = scol[i + 1];
            const int   c2 = scol[i + 2], c3 = scol[i + 3];
            const float w0 = w[(size_t)c0 * OUT_UNITS + tid];
            const float w1 = w[(size_t)c1 * OUT_UNITS + tid];
            const float w2 = w[(size_t)c2 * OUT_UNITS + tid];
            const float w3 = w[(size_t)c3 * OUT_UNITS + tid];
            acc = fmaf(v0, w0, acc);
            acc = fmaf(v1, w1, acc);
            acc = fmaf(v2, w2, acc);
            acc = fmaf(v3, w3, acc);
        }
        for (; i < m; i++) {
            acc = fmaf(sval[i], w[(size_t)scol[i] * OUT_UNITS + tid], acc);
        }
        __syncthreads();
    }

    out[(size_t)r * OUT_UNITS + tid] = acc;
}

// ---------------------------------------------------------------------------
// Launch
// Inputs (metadata order): values f32[NNZ], w f32[8192*128],
//                          rows int{32,64}[NNZ], cols int{32,64}[NNZ], n_rows
// ---------------------------------------------------------------------------
extern "C" void kernel_launch(void* const* d_in, const int* in_sizes, int n_in,
                              void* d_out, int out_size) {
    const float* values = (const float*)d_in[0];
    const float* w      = (const float*)d_in[1];
    const int*   rows32 = (const int*)d_in[2];
    const int*   cols32 = (const int*)d_in[3];
    float*       out    = (float*)d_out;

    const int nnz    = in_sizes[0];
    const int n_rows = out_size / OUT_UNITS;

    detect_dtype_kernel<<<1, 1>>>(rows32, nnz);

    const int bs = 256;
    build_offsets_kernel<<<(nnz + bs - 1) / bs, bs>>>(rows32, nnz, n_rows);

    spmm_kernel<<<n_rows, OUT_UNITS>>>(values, w, cols32, out);
}

// round 2
// speedup vs baseline: 1.4310x; 1.4310x over previous
#include <cuda_runtime.h>
#include <cuda_bf16.h>

#define OUT_UNITS 128
#define MAX_ROWS  16384
#define WARPS_PER_BLOCK 8

// ---------------------------------------------------------------------------
// Scratch (device globals — no allocation allowed in kernel_launch)
// ---------------------------------------------------------------------------
__device__ int g_is64;                       // 1 if rows/cols are int64, 0 if int32
__device__ int g_row_start[MAX_ROWS + 1];    // CSR-style row offsets

// ---------------------------------------------------------------------------
// Dtype probe (device helper): rows sorted ascending over [0, 16384).
// If int64 (little-endian), every odd 32-bit word is a zero high-half.
// If int32, odd words near n/4, n/2, 3n/4 are sorted row ids ~4096/8192/12288.
// All probed indices are odd and < n: in-bounds for both layouts.
// ---------------------------------------------------------------------------
__device__ __forceinline__ int probe_is64(const int* __restrict__ rows32, int n) {
    int j1 = (n / 2) | 1;
    int j2 = (n / 4) | 1;
    int j3 = (int)(((long long)3 * n) / 4) | 1;
    int s = rows32[j1] | rows32[j2] | rows32[j3];
    return (s == 0) ? 1 : 0;
}

// ---------------------------------------------------------------------------
// Kernel 1: build row offsets from sorted COO rows (fused dtype detection).
// Segment for row r is [g_row_start[r], g_row_start[r+1]).
// ---------------------------------------------------------------------------
__global__ void build_offsets_kernel(const int* __restrict__ rows32, int nnz, int n_rows) {
    const int is64 = probe_is64(rows32, nnz);   // 3 loads, L1/L2 broadcast-hot

    int k = blockIdx.x * blockDim.x + threadIdx.x;
    if (k == 0) g_is64 = is64;                  // publish for spmm (next launch)
    if (k >= nnz) return;

    int r  = is64 ? rows32[2 * k] : rows32[k];
    int rp = (k == 0) ? -1 : (is64 ? rows32[2 * (k - 1)] : rows32[k - 1]);

    for (int j = rp + 1; j <= r && j <= n_rows; j++)
        g_row_start[j] = k;

    if (k == nnz - 1) {
        for (int j = r + 1; j <= n_rows; j++)
            g_row_start[j] = nnz;
    }
}

// ---------------------------------------------------------------------------
// Kernel 2: main SpMM. One WARP per output row; lane t owns output columns
// [4t, 4t+4) via float4. Stage 32 (val, col) pairs per warp in smem (LDS.64
// broadcast reads), then gather W rows with LDG.128 (1 warp-inst / 512B / nnz),
// 4-way unrolled for 16 L2 sectors in flight per warp.
// ---------------------------------------------------------------------------
__global__ void __launch_bounds__(32 * WARPS_PER_BLOCK)
spmm_kernel(const float* __restrict__ values,
            const float* __restrict__ w,
            const int*   __restrict__ cols32,
            float*       __restrict__ out) {
    const int warp = threadIdx.x >> 5;
    const int lane = threadIdx.x & 31;
    const int r    = blockIdx.x * WARPS_PER_BLOCK + warp;
    const int is64 = g_is64;

    __shared__ float2 stage[WARPS_PER_BLOCK][32];

    const int lo = g_row_start[r];
    const int hi = g_row_start[r + 1];

    float4 acc = make_float4(0.f, 0.f, 0.f, 0.f);
    const float4* __restrict__ w4 = (const float4*)w;   // w4[c*32 + lane]

    for (int base = lo; base < hi; base += 32) {
        const int m = min(32, hi - base);
        if (lane < m) {
            const int k = base + lane;
            const int c = is64 ? cols32[2 * k] : cols32[k];
            stage[warp][lane] = make_float2(values[k], __int_as_float(c));
        }
        __syncwarp();

        int i = 0;
        #pragma unroll 1
        for (; i + 4 <= m; i += 4) {
            const float2 p0 = stage[warp][i + 0];
            const float2 p1 = stage[warp][i + 1];
            const float2 p2 = stage[warp][i + 2];
            const float2 p3 = stage[warp][i + 3];
            // 4 independent LDG.128s in flight (16 L2 sectors per warp)
            const float4 w0 = w4[(size_t)__float_as_int(p0.y) * 32 + lane];
            const float4 w1 = w4[(size_t)__float_as_int(p1.y) * 32 + lane];
            const float4 w2 = w4[(size_t)__float_as_int(p2.y) * 32 + lane];
            const float4 w3 = w4[(size_t)__float_as_int(p3.y) * 32 + lane];
            acc.x = fmaf(p0.x, w0.x, acc.x); acc.y = fmaf(p0.x, w0.y, acc.y);
            acc.z = fmaf(p0.x, w0.z, acc.z); acc.w = fmaf(p0.x, w0.w, acc.w);
            acc.x = fmaf(p1.x, w1.x, acc.x); acc.y = fmaf(p1.x, w1.y, acc.y);
            acc.z = fmaf(p1.x, w1.z, acc.z); acc.w = fmaf(p1.x, w1.w, acc.w);
            acc.x = fmaf(p2.x, w2.x, acc.x); acc.y = fmaf(p2.x, w2.y, acc.y);
            acc.z = fmaf(p2.x, w2.z, acc.z); acc.w = fmaf(p2.x, w2.w, acc.w);
            acc.x = fmaf(p3.x, w3.x, acc.x); acc.y = fmaf(p3.x, w3.y, acc.y);
            acc.z = fmaf(p3.x, w3.z, acc.z); acc.w = fmaf(p3.x, w3.w, acc.w);
        }
        for (; i < m; i++) {
            const float2 p = stage[warp][i];
            const float4 wv = w4[(size_t)__float_as_int(p.y) * 32 + lane];
            acc.x = fmaf(p.x, wv.x, acc.x); acc.y = fmaf(p.x, wv.y, acc.y);
            acc.z = fmaf(p.x, wv.z, acc.z); acc.w = fmaf(p.x, wv.w, acc.w);
        }
        __syncwarp();
    }

    ((float4*)out)[(size_t)r * 32 + lane] = acc;
}

// ---------------------------------------------------------------------------
// Launch
// Inputs (metadata order): values f32[NNZ], w f32[8192*128],
//                          rows int{32,64}[NNZ], cols int{32,64}[NNZ], n_rows
// ---------------------------------------------------------------------------
extern "C" void kernel_launch(void* const* d_in, const int* in_sizes, int n_in,
                              void* d_out, int out_size) {
    const float* values = (const float*)d_in[0];
    const float* w      = (const float*)d_in[1];
    const int*   rows32 = (const int*)d_in[2];
    const int*   cols32 = (const int*)d_in[3];
    float*       out    = (float*)d_out;

    const int nnz    = in_sizes[0];
    const int n_rows = out_size / OUT_UNITS;

    const int bs = 256;
    build_offsets_kernel<<<(nnz + bs - 1) / bs, bs>>>(rows32, nnz, n_rows);

    spmm_kernel<<<n_rows / WARPS_PER_BLOCK, 32 * WARPS_PER_BLOCK>>>(values, w, cols32, out);
}